// round 8
// baseline (speedup 1.0000x reference)
#include <cuda_runtime.h>

// y = min(((x + 1) * 0.75)^2, 10)  — elementwise over 8192*8192 fp32.
// HBM-bound stream at sustained roofline. Blackwell 256-bit global accesses:
// 2 front-batched ld.global.v8.f32 per thread (64B in flight, same depth as
// proven MLP-4 x 128-bit), 2 st.global.v8.f32. Warp covers 1KB contiguous per
// instruction. 67108864 elems = 16384 blocks * 256 thr * 16 elems (exact).

#define T 256u

__device__ __forceinline__ float f(float x) {
    float t = (x + 1.0f) * 0.75f;
    float y = t * t;
    return fminf(y, 10.0f);
}

struct V8 { float v[8]; };

__device__ __forceinline__ V8 ldg256(const float* p) {
    V8 r;
    asm volatile("ld.global.v8.f32 {%0,%1,%2,%3,%4,%5,%6,%7}, [%8];"
                 : "=f"(r.v[0]), "=f"(r.v[1]), "=f"(r.v[2]), "=f"(r.v[3]),
                   "=f"(r.v[4]), "=f"(r.v[5]), "=f"(r.v[6]), "=f"(r.v[7])
                 : "l"(p));
    return r;
}

__device__ __forceinline__ void stg256(float* p, const V8& r) {
    asm volatile("st.global.v8.f32 [%0], {%1,%2,%3,%4,%5,%6,%7,%8};"
                 :: "l"(p),
                    "f"(r.v[0]), "f"(r.v[1]), "f"(r.v[2]), "f"(r.v[3]),
                    "f"(r.v[4]), "f"(r.v[5]), "f"(r.v[6]), "f"(r.v[7])
                 : "memory");
}

__device__ __forceinline__ V8 f8(V8 a) {
    V8 r;
#pragma unroll
    for (int i = 0; i < 8; i++) r.v[i] = f(a.v[i]);
    return r;
}

__global__ __launch_bounds__(256) void elemwise_kernel(const float* __restrict__ in,
                                                       float* __restrict__ out) {
    // Each block handles T*16 floats; thread t owns two 8-float chunks at
    // blockDim stride (coalesced: warp covers 1KB contiguous per access).
    unsigned base = blockIdx.x * (T * 16u) + threadIdx.x * 8u;

    V8 a = ldg256(in + base);
    V8 b = ldg256(in + base + T * 8u);

    stg256(out + base,          f8(a));
    stg256(out + base + T * 8u, f8(b));
}

extern "C" void kernel_launch(void* const* d_in, const int* in_sizes, int n_in,
                              void* d_out, int out_size) {
    const float* in = (const float*)d_in[0];
    float* out = (float*)d_out;
    int n = in_sizes[0];           // 67108864
    int blocks = n / (256 * 16);   // 16384, exact
    elemwise_kernel<<<blocks, 256>>>(in, out);
}

// round 9
// speedup vs baseline: 1.0051x; 1.0051x over previous
#include <cuda_runtime.h>

// y = min(((x + 1) * 0.75)^2, 10)  — elementwise over 8192*8192 fp32.
// FINAL: best-measured configuration (R5). HBM-bound at the sustained
// power-limited roofline (~6.4 TB/s on 512MB irreducible traffic).
// 4 independent front-batched float4 loads per thread (MLP_p1=4, the
// measured saturation point), default cache ops, coalesced at blockDim
// stride, 512-thread blocks. 67108864 elems = 8192 blocks * 512 thr * 16.
//
// Measured across 8 rounds: all streaming structures land within noise of
// this point (wall 82.0-82.7us); streaming cache hints and persistent grids
// regress. This is the roofline.

#define T 512u

__device__ __forceinline__ float f(float x) {
    float t = (x + 1.0f) * 0.75f;
    float y = t * t;
    return fminf(y, 10.0f);
}

__device__ __forceinline__ float4 f4(float4 v) {
    float4 r;
    r.x = f(v.x); r.y = f(v.y); r.z = f(v.z); r.w = f(v.w);
    return r;
}

__global__ __launch_bounds__(512) void elemwise_kernel(const float4* __restrict__ in,
                                                       float4* __restrict__ out) {
    unsigned base = blockIdx.x * (T * 4u) + threadIdx.x;

    // Front-batch 4 independent loads -> MLP=4.
    float4 v0 = in[base + 0u * T];
    float4 v1 = in[base + 1u * T];
    float4 v2 = in[base + 2u * T];
    float4 v3 = in[base + 3u * T];

    out[base + 0u * T] = f4(v0);
    out[base + 1u * T] = f4(v1);
    out[base + 2u * T] = f4(v2);
    out[base + 3u * T] = f4(v3);
}

extern "C" void kernel_launch(void* const* d_in, const int* in_sizes, int n_in,
                              void* d_out, int out_size) {
    const float4* in = (const float4*)d_in[0];
    float4* out = (float4*)d_out;
    int n = in_sizes[0];            // 67108864
    int n4 = n / 4;                 // 16777216 float4s
    int blocks = n4 / (512 * 4);    // 8192, exact
    elemwise_kernel<<<blocks, 512>>>(in, out);
}

// round 10
// speedup vs baseline: 1.0055x; 1.0004x over previous
#include <cuda_runtime.h>

// y = min(((x + 1) * 0.75)^2, 10)  — elementwise over 8192*8192 fp32.
// FINAL (locked in after 9 measured rounds). HBM-bound at the sustained
// power-limited roofline: ~6.45 TB/s on 512MB irreducible traffic ->
// ~80us floor; this kernel measures 74.4us ncu / 82.0-82.2us wall.
//
// Structure: 4 independent front-batched float4 loads per thread
// (MLP_p1=4 — measured saturation point; MLP=8 trades occupancy for zero
// gain), default cache ops (streaming hints regressed), coalesced at
// blockDim stride, 512-thread blocks, many blocks for HW load balancing
// (persistent grid regressed). 67108864 = 8192 blocks * 512 thr * 16 elems.

#define T 512u

__device__ __forceinline__ float f(float x) {
    float t = (x + 1.0f) * 0.75f;
    float y = t * t;
    return fminf(y, 10.0f);
}

__device__ __forceinline__ float4 f4(float4 v) {
    float4 r;
    r.x = f(v.x); r.y = f(v.y); r.z = f(v.z); r.w = f(v.w);
    return r;
}

__global__ __launch_bounds__(512) void elemwise_kernel(const float4* __restrict__ in,
                                                       float4* __restrict__ out) {
    unsigned base = blockIdx.x * (T * 4u) + threadIdx.x;

    // Front-batch 4 independent loads -> MLP=4.
    float4 v0 = in[base + 0u * T];
    float4 v1 = in[base + 1u * T];
    float4 v2 = in[base + 2u * T];
    float4 v3 = in[base + 3u * T];

    out[base + 0u * T] = f4(v0);
    out[base + 1u * T] = f4(v1);
    out[base + 2u * T] = f4(v2);
    out[base + 3u * T] = f4(v3);
}

extern "C" void kernel_launch(void* const* d_in, const int* in_sizes, int n_in,
                              void* d_out, int out_size) {
    const float4* in = (const float4*)d_in[0];
    float4* out = (float4*)d_out;
    int n = in_sizes[0];            // 67108864
    int n4 = n / 4;                 // 16777216 float4s
    int blocks = n4 / (512 * 4);    // 8192, exact
    elemwise_kernel<<<blocks, 512>>>(in, out);
}

// round 11
// speedup vs baseline: 1.0074x; 1.0020x over previous
#include <cuda_runtime.h>

// y = min(((x + 1) * 0.75)^2, 10)  — elementwise over 8192*8192 fp32.
// FINAL — verified stable across 3 consecutive reproductions
// (wall 82.0-82.2us, ncu 74.4-74.6us, DRAM 81.5-81.7%, 6.46-6.47 TB/s).
//
// HBM-bound at the sustained power-limited roofline: 512MB irreducible
// traffic / ~6.45 TB/s sustained ≈ 80us floor; this kernel is within ~3%
// of it including launch overhead.
//
// Structure (each choice measured against alternatives over 10 rounds):
//  - 4 independent front-batched float4 loads per thread (MLP_p1=4 is the
//    measured saturation point; MLP=8 costs occupancy for zero gain)
//  - default cache operators (__ldcs/__stcs streaming hints regressed)
//  - coalesced blockDim-stride addressing (warp = contiguous 128B segments)
//  - 512-thread blocks, 8192 blocks; many small blocks beat a persistent
//    grid (HW work-stealing balances better than static partitioning)
//  - exact grid: 67108864 = 8192 * 512 * 16, no bounds checks

#define T 512u

__device__ __forceinline__ float f(float x) {
    float t = (x + 1.0f) * 0.75f;
    float y = t * t;
    return fminf(y, 10.0f);
}

__device__ __forceinline__ float4 f4(float4 v) {
    float4 r;
    r.x = f(v.x); r.y = f(v.y); r.z = f(v.z); r.w = f(v.w);
    return r;
}

__global__ __launch_bounds__(512) void elemwise_kernel(const float4* __restrict__ in,
                                                       float4* __restrict__ out) {
    unsigned base = blockIdx.x * (T * 4u) + threadIdx.x;

    // Front-batch 4 independent loads -> MLP=4.
    float4 v0 = in[base + 0u * T];
    float4 v1 = in[base + 1u * T];
    float4 v2 = in[base + 2u * T];
    float4 v3 = in[base + 3u * T];

    out[base + 0u * T] = f4(v0);
    out[base + 1u * T] = f4(v1);
    out[base + 2u * T] = f4(v2);
    out[base + 3u * T] = f4(v3);
}

extern "C" void kernel_launch(void* const* d_in, const int* in_sizes, int n_in,
                              void* d_out, int out_size) {
    const float4* in = (const float4*)d_in[0];
    float4* out = (float4*)d_out;
    int n = in_sizes[0];            // 67108864
    int n4 = n / 4;                 // 16777216 float4s
    int blocks = n4 / (512 * 4);    // 8192, exact
    elemwise_kernel<<<blocks, 512>>>(in, out);
}